// round 5
// baseline (speedup 1.0000x reference)
#include <cuda_runtime.h>

#define NB 256
#define NT 1024
#define NV 5000
#define ND 100
#define NH 64
#define NC 2

// Scratch: EW = E @ W + b, [V, H]. 1.28 MB -> fully L2-resident.
__device__ float g_EWb[NV * NH];

// ---------------------------------------------------------------------------
// Kernel A: EWb[v][j] = sum_d E[v][d] * W[d][j] + b[j]
// ---------------------------------------------------------------------------
__global__ void ew_kernel(const float* __restrict__ E,
                          const float* __restrict__ W,
                          const float* __restrict__ bias) {
    int v = blockIdx.x * 4 + (threadIdx.x >> 6);
    int j = threadIdx.x & 63;
    if (v >= NV) return;
    float acc = bias[j];
    const float* e = E + v * ND;
    #pragma unroll 4
    for (int d = 0; d < ND; d++)
        acc = fmaf(e[d], W[d * NH + j], acc);
    g_EWb[v * NH + j] = acc;
}

typedef unsigned long long u64;

__device__ __forceinline__ u64 ffma2(u64 a, u64 b, u64 c) {
    u64 d;
    asm("fma.rn.f32x2 %0, %1, %2, %3;" : "=l"(d) : "l"(a), "l"(b), "l"(c));
    return d;
}
__device__ __forceinline__ u64 fadd2(u64 a, u64 b) {
    u64 d;
    asm("add.rn.f32x2 %0, %1, %2;" : "=l"(d) : "l"(a), "l"(b));
    return d;
}
__device__ __forceinline__ u64 pk2(float x, float y) {
    u64 r;
    asm("mov.b64 %0, {%1, %2};" : "=l"(r) : "f"(x), "f"(y));
    return r;
}
__device__ __forceinline__ void upk2(u64 v, float& x, float& y) {
    asm("mov.b64 {%0, %1}, %2;" : "=f"(x), "=f"(y) : "l"(v));
}
// HW tanh (MUFU.TANH): lat 16, single instruction, ~2^-11 error.
__device__ __forceinline__ float tanh_fast(float x) {
    float y;
    asm("tanh.approx.f32 %0, %1;" : "=f"(y) : "f"(x));
    return y;
}

// ---------------------------------------------------------------------------
// Kernel B: masked tanh RNN, T=1024 steps + mean-pool + dense + sigmoid.
// ONE BLOCK (128 threads = 4 warps) PER ROW. K-split by 2 in-warp: lanes
// (l, l+16) of warp w own output j = 16w + (l&15); lane's K-half = l>>4.
// Dot product via 16 packed fma.rn.f32x2 (even/odd-k partial pairs, operands
// in natural memory order from LDS.128). Partials merge with one
// shfl.bfly(16); ew folded into the low-half accumulator pre-loop; the mask
// predicate is precomputed 2 steps ahead so the h-select is a pure FSEL.
// One __syncthreads per step; explicit 2-step unroll for buffer ping-pong.
// ---------------------------------------------------------------------------
__global__ void __launch_bounds__(128) rnn_kernel(
    const int* __restrict__ tokens,
    const float* __restrict__ U,
    const float* __restrict__ Wd,
    const float* __restrict__ bd,
    float* __restrict__ out)
{
    __shared__ __align__(16) float hbuf[2][NH];
    __shared__ float red[4][2];
    const int w     = threadIdx.x >> 5;
    const int l     = threadIdx.x & 31;
    const int j     = w * 16 + (l & 15);
    const int kbase = (l >> 4) * 32;
    const bool low  = (l < 16);
    const int b     = blockIdx.x;

    // U K-pairs for this lane's half: Upk[m] = (U[kbase+2m][j], U[kbase+2m+1][j]).
    u64 Upk[16];
    #pragma unroll
    for (int m = 0; m < 16; m++) {
        float ua = U[(kbase + 2 * m)     * NH + j];
        float ub = U[(kbase + 2 * m + 1) * NH + j];
        Upk[m] = pk2(ua, ub);
    }

    if (threadIdx.x < NH) hbuf[0][threadIdx.x] = 0.f;
    __syncthreads();

    const int* trow = tokens + b * NT;
    float h = 0.f, s = 0.f;

    // Pipeline state: ew 2 ahead, mask 2 ahead, token 3 ahead.
    int   ta = trow[0], tb = trow[1], tc = trow[2];
    float ew_cur = g_EWb[ta * NH + j];
    float ew_nxt = g_EWb[tb * NH + j];
    bool  m_cur = (ta != 0), m_nxt = (tb != 0), m_n2 = (tc != 0);
    int   tk = tc;                       // token[t+2], feeds ew load

    #define RNN_STEP(SRC, DST, T)                                             \
    {                                                                         \
        float ew_new = g_EWb[tk * NH + j];                                    \
        bool  m_new  = (tk != 0);                                             \
        int   t3 = (T) + 3; if (t3 >= NT) t3 = NT - 1;                        \
        int   tk_new = trow[t3];                                              \
        float ewsel  = low ? ew_cur : 0.f;                                    \
        const ulonglong2* hp = reinterpret_cast<const ulonglong2*>((SRC) + kbase); \
        ulonglong2 h0 = hp[0], h1 = hp[1], h2 = hp[2], h3 = hp[3];            \
        ulonglong2 h4 = hp[4], h5 = hp[5], h6 = hp[6], h7 = hp[7];            \
        u64 A0 = pk2(ewsel, 0.f);                                             \
        u64 A1 = 0ull, A2 = 0ull, A3 = 0ull;                                  \
        u64 A4 = 0ull, A5 = 0ull, A6 = 0ull, A7 = 0ull;                       \
        A0 = ffma2(h0.x, Upk[0],  A0);  A1 = ffma2(h0.y, Upk[1],  A1);        \
        A2 = ffma2(h1.x, Upk[2],  A2);  A3 = ffma2(h1.y, Upk[3],  A3);        \
        A4 = ffma2(h2.x, Upk[4],  A4);  A5 = ffma2(h2.y, Upk[5],  A5);        \
        A6 = ffma2(h3.x, Upk[6],  A6);  A7 = ffma2(h3.y, Upk[7],  A7);        \
        A0 = ffma2(h4.x, Upk[8],  A0);  A1 = ffma2(h4.y, Upk[9],  A1);        \
        A2 = ffma2(h5.x, Upk[10], A2);  A3 = ffma2(h5.y, Upk[11], A3);        \
        A4 = ffma2(h6.x, Upk[12], A4);  A5 = ffma2(h6.y, Upk[13], A5);        \
        A6 = ffma2(h7.x, Upk[14], A6);  A7 = ffma2(h7.y, Upk[15], A7);        \
        u64 S = fadd2(fadd2(fadd2(A0, A1), fadd2(A2, A3)),                    \
                      fadd2(fadd2(A4, A5), fadd2(A6, A7)));                   \
        float sx_, sy_;                                                       \
        upk2(S, sx_, sy_);                                                    \
        float p_ = sx_ + sy_;                                                 \
        float a_ = p_ + __shfl_xor_sync(0xffffffffu, p_, 16);                 \
        float hn = tanh_fast(a_);                                             \
        h = m_cur ? hn : h;                                                   \
        if (low) (DST)[j] = h;                                                \
        s += h;                                                               \
        m_cur = m_nxt; m_nxt = m_n2; m_n2 = m_new;                            \
        ew_cur = ew_nxt; ew_nxt = ew_new;                                     \
        tk = tk_new;                                                          \
        __syncthreads();                                                      \
    }

    for (int t = 0; t < NT; t += 2) {
        RNN_STEP(hbuf[0], hbuf[1], t);
        RNN_STEP(hbuf[1], hbuf[0], t + 1);
    }
    #undef RNN_STEP

    // Epilogue: mean pool -> dense (64 -> 2) -> sigmoid. Output j is held by
    // 2 lanes; count only l<16.
    float p  = s * (1.0f / NT);
    float c0 = low ? p * Wd[j * NC + 0] : 0.f;
    float c1 = low ? p * Wd[j * NC + 1] : 0.f;
    #pragma unroll
    for (int off = 16; off; off >>= 1) {
        c0 += __shfl_xor_sync(0xffffffffu, c0, off);
        c1 += __shfl_xor_sync(0xffffffffu, c1, off);
    }
    if (l == 0) { red[w][0] = c0; red[w][1] = c1; }
    __syncthreads();
    if (threadIdx.x == 0) {
        float C0 = red[0][0] + red[1][0] + red[2][0] + red[3][0] + bd[0];
        float C1 = red[0][1] + red[1][1] + red[2][1] + red[3][1] + bd[1];
        out[b * NC + 0] = 1.0f / (1.0f + expf(-C0));
        out[b * NC + 1] = 1.0f / (1.0f + expf(-C1));
    }
}

// ---------------------------------------------------------------------------
extern "C" void kernel_launch(void* const* d_in, const int* in_sizes, int n_in,
                              void* d_out, int out_size) {
    const int*   tokens = (const int*)  d_in[0];
    const float* E      = (const float*)d_in[1];
    const float* W      = (const float*)d_in[2];
    const float* U      = (const float*)d_in[3];
    const float* bias   = (const float*)d_in[4];
    const float* Wd     = (const float*)d_in[5];
    const float* bd     = (const float*)d_in[6];
    float* out = (float*)d_out;

    ew_kernel<<<(NV + 3) / 4, 256>>>(E, W, bias);
    rnn_kernel<<<NB, 128>>>(tokens, U, Wd, bd, out);
}